// round 3
// baseline (speedup 1.0000x reference)
#include <cuda_runtime.h>
#include <cuda_fp16.h>

#define B_    8
#define SENC  256
#define SDEC  128
#define U_    512
#define DIM   512

// ------------------------- scratch (device globals, no alloc) -------------
__device__ __align__(16) __half g_denc_h[B_ * SENC * U_];   // 2 MB
__device__ __align__(16) __half g_ddec_h[B_ * SDEC * U_];   // 1 MB
__device__ __align__(16) __half g_wh[U_];

// ------------------------- helpers ----------------------------------------
__device__ __forceinline__ __half2 atk_tanh_h2(__half2 x) {
    __half2 y;
    asm("tanh.approx.f16x2 %0, %1;"
        : "=r"(reinterpret_cast<unsigned&>(y))
        : "r"(reinterpret_cast<unsigned const&>(x)));
    return y;
}

// ------------------------- GEMM: C(half) = A[M,512] @ W[512,512] + bias ----
// BM=BN=64, BK=16, 256 threads, 4x4 micro-tile.
__global__ void __launch_bounds__(256) sgemm_bias_half(
    const float* __restrict__ A, const float* __restrict__ W,
    const float* __restrict__ bias, int which /*0->g_denc_h, 1->g_ddec_h*/)
{
    __half* __restrict__ C = which ? g_ddec_h : g_denc_h;
    const int N = 512, K = 512;
    __shared__ float As[16][68];
    __shared__ float Bs[16][68];

    int t  = threadIdx.x;
    int tx = t & 15, ty = t >> 4;
    int bm = blockIdx.x * 64, bn = blockIdx.y * 64;

    int ar = t >> 2, ac = (t & 3) << 2;   // A-tile: row 0..63, k-col group
    int br = t >> 4, bc = (t & 15) << 2;  // W-tile: k-row 0..15, col group

    const float* Ag = A + (size_t)(bm + ar) * K + ac;
    const float* Wg = W + (size_t)br * N + bn + bc;

    float acc[4][4] = {};

    for (int k0 = 0; k0 < K; k0 += 16) {
        float4 av = *(const float4*)(Ag + k0);
        float4 bv = *(const float4*)(Wg + (size_t)k0 * N);
        As[ac + 0][ar] = av.x; As[ac + 1][ar] = av.y;
        As[ac + 2][ar] = av.z; As[ac + 3][ar] = av.w;
        *(float4*)&Bs[br][bc] = bv;
        __syncthreads();
#pragma unroll
        for (int kk = 0; kk < 16; kk++) {
            float a[4], b[4];
            *(float4*)a = *(const float4*)&As[kk][ty << 2];
            *(float4*)b = *(const float4*)&Bs[kk][tx << 2];
#pragma unroll
            for (int i = 0; i < 4; i++)
#pragma unroll
                for (int j = 0; j < 4; j++)
                    acc[i][j] = fmaf(a[i], b[j], acc[i][j]);
        }
        __syncthreads();
    }

#pragma unroll
    for (int j = 0; j < 4; j++) {
        float bj = bias[bn + (tx << 2) + j];
#pragma unroll
        for (int i = 0; i < 4; i++) {
            int row = bm + (ty << 2) + i;
            C[(size_t)row * N + bn + (tx << 2) + j] =
                __float2half_rn(acc[i][j] + bj);
        }
    }
}

// ------------------------- W_score fp32 -> fp16 ----------------------------
__global__ void wconv(const float* __restrict__ ws)
{
    int i = blockIdx.x * 256 + threadIdx.x;
    if (i < U_) g_wh[i] = __float2half_rn(ws[i]);
}

// ------------------------- fused scores + softmax + context ----------------
// Block = (b, q-group of 4). 256 threads = 8 warps; warps 2k,2k+1 handle q=k.
// Lane l owns u indices {2l,2l+1, 2l+64,... } i.e. half2 slots l+32j (4B lane
// stride -> conflict-free LDS.32 everywhere).
#define ETILE  64   // d_enc rows per smem tile (fp16): 64*512*2 = 64 KB
#define E2TILE 32   // enc rows per smem tile (fp32): 32*512*4 = 64 KB

extern __shared__ char smem_raw[];

__global__ void __launch_bounds__(256) fused_attn(
    const float* __restrict__ enc, float* __restrict__ out)
{
    __half2* s_de  = (__half2*)smem_raw;            // [ETILE*256] half2
    float*   s_enc = (float*)smem_raw;              // union: [E2TILE*512]
    float*   s_w   = (float*)(smem_raw + 65536);    // [4*256] scores->weights
    __shared__ float s_red[16];

    int t  = threadIdx.x;
    int l  = t & 31, w = t >> 5;
    int qg = blockIdx.x, b = blockIdx.y;
    int wq = w >> 1, p = w & 1;
    int qrow = b * SDEC + qg * 4 + wq;

    // per-lane decoder projection + score weights (half2, interleaved layout)
    __half2 dd2[8], wv[8];
    {
        const __half2* ddp = (const __half2*)g_ddec_h + (size_t)qrow * 256;
        const __half2* wp  = (const __half2*)g_wh;
#pragma unroll
        for (int j = 0; j < 8; j++) {
            dd2[j] = ddp[l + 32 * j];
            wv[j]  = wp[l + 32 * j];
        }
    }

    // ---- phase 1: scores ----
    const uint4* de_g = (const uint4*)(g_denc_h + (size_t)b * SENC * U_);
    for (int et = 0; et < SENC / ETILE; et++) {
        __syncthreads();
        {
            const uint4* src = de_g + (size_t)et * ETILE * 64;
            uint4* dst = (uint4*)s_de;
#pragma unroll
            for (int i = 0; i < (ETILE * 64) / 256; i++)
                dst[t + 256 * i] = src[t + 256 * i];
        }
        __syncthreads();
        for (int ei = 0; ei < 32; ei++) {
            int eL = p * 32 + ei;
            const __half2* der = s_de + eL * 256;
            __half2 a0 = __float2half2_rn(0.f), a1 = a0;
#pragma unroll
            for (int j = 0; j < 8; j++) {
                __half2 x  = __hadd2(dd2[j], der[l + 32 * j]);
                __half2 th = atk_tanh_h2(x);
                if (j & 1) a1 = __hfma2(th, wv[j], a1);
                else       a0 = __hfma2(th, wv[j], a0);
            }
            float2 f0 = __half22float2(a0), f1 = __half22float2(a1);
            float s = (f0.x + f0.y) + (f1.x + f1.y);
#pragma unroll
            for (int o = 16; o > 0; o >>= 1)
                s += __shfl_xor_sync(0xffffffffu, s, o);
            if (l == 0) s_w[wq * 256 + et * ETILE + eL] = s;
        }
    }
    __syncthreads();

    // ---- softmax over 256 encoder positions, 64 threads per q ----
    int qs = t >> 6, idx = t & 63;
    float v0 = s_w[qs * 256 + idx],       v1 = s_w[qs * 256 + idx + 64];
    float v2 = s_w[qs * 256 + idx + 128], v3 = s_w[qs * 256 + idx + 192];
    float m = fmaxf(fmaxf(v0, v1), fmaxf(v2, v3));
#pragma unroll
    for (int o = 16; o > 0; o >>= 1)
        m = fmaxf(m, __shfl_xor_sync(0xffffffffu, m, o));
    if (l == 0) s_red[w] = m;
    __syncthreads();
    m = fmaxf(s_red[qs * 2], s_red[qs * 2 + 1]);
    float e0 = __expf(v0 - m), e1 = __expf(v1 - m);
    float e2 = __expf(v2 - m), e3 = __expf(v3 - m);
    float sum = (e0 + e1) + (e2 + e3);
#pragma unroll
    for (int o = 16; o > 0; o >>= 1)
        sum += __shfl_xor_sync(0xffffffffu, sum, o);
    if (l == 0) s_red[8 + w] = sum;
    __syncthreads();
    float inv = 1.f / (s_red[8 + qs * 2] + s_red[8 + qs * 2 + 1]);
    s_w[qs * 256 + idx]       = e0 * inv;
    s_w[qs * 256 + idx + 64]  = e1 * inv;
    s_w[qs * 256 + idx + 128] = e2 * inv;
    s_w[qs * 256 + idx + 192] = e3 * inv;

    // ---- phase 2: contexts = weights @ encodings ----
    // thread owns q2 = t>>6, d = {g*4..+3} and {256+g*4..+3}
    int q2 = qs, g = idx;
    float acc0[4] = {}, acc1[4] = {};
    const float* encb = enc + (size_t)b * SENC * DIM;
    for (int et = 0; et < SENC / E2TILE; et++) {
        __syncthreads();   // also orders weight writes & smem union reuse
        {
            const float4* src = (const float4*)(encb + (size_t)et * E2TILE * DIM);
            float4* dst = (float4*)s_enc;
#pragma unroll
            for (int i = 0; i < (E2TILE * DIM / 4) / 256; i++)
                dst[t + 256 * i] = src[t + 256 * i];
        }
        __syncthreads();
#pragma unroll 4
        for (int el = 0; el < E2TILE; el++) {
            float wgt = s_w[q2 * 256 + et * E2TILE + el];
            const float* er = s_enc + el * DIM;
            float4 x0 = *(const float4*)(er + g * 4);
            float4 x1 = *(const float4*)(er + 256 + g * 4);
            acc0[0] = fmaf(wgt, x0.x, acc0[0]);
            acc0[1] = fmaf(wgt, x0.y, acc0[1]);
            acc0[2] = fmaf(wgt, x0.z, acc0[2]);
            acc0[3] = fmaf(wgt, x0.w, acc0[3]);
            acc1[0] = fmaf(wgt, x1.x, acc1[0]);
            acc1[1] = fmaf(wgt, x1.y, acc1[1]);
            acc1[2] = fmaf(wgt, x1.z, acc1[2]);
            acc1[3] = fmaf(wgt, x1.w, acc1[3]);
        }
    }

    float* orow = out + (size_t)(b * SDEC + qg * 4 + q2) * DIM;
    *(float4*)(orow + g * 4)       = make_float4(acc0[0], acc0[1], acc0[2], acc0[3]);
    *(float4*)(orow + 256 + g * 4) = make_float4(acc1[0], acc1[1], acc1[2], acc1[3]);
}

// ------------------------- launch ------------------------------------------
extern "C" void kernel_launch(void* const* d_in, const int* in_sizes, int n_in,
                              void* d_out, int out_size)
{
    (void)in_sizes; (void)n_in; (void)out_size;
    const float* enc    = (const float*)d_in[0];
    const float* dec    = (const float*)d_in[1];
    const float* Wenc   = (const float*)d_in[2];
    const float* Wdec   = (const float*)d_in[3];
    const float* Wscore = (const float*)d_in[4];
    const float* benc   = (const float*)d_in[5];
    const float* bdec   = (const float*)d_in[6];
    float* out = (float*)d_out;

    // projections -> fp16 scratch
    sgemm_bias_half<<<dim3((B_ * SENC) / 64, U_ / 64), 256>>>(enc, Wenc, benc, 0);
    sgemm_bias_half<<<dim3((B_ * SDEC) / 64, U_ / 64), 256>>>(dec, Wdec, bdec, 1);
    wconv<<<2, 256>>>(Wscore);

    const int SMEM = 65536 + 4096;  // de/enc tile union + weights
    cudaFuncSetAttribute(fused_attn,
                         cudaFuncAttributeMaxDynamicSharedMemorySize, SMEM);
    fused_attn<<<dim3(SDEC / 4, B_), 256, SMEM>>>(enc, out);
}